// round 6
// baseline (speedup 1.0000x reference)
#include <cuda_runtime.h>
#include <cuda_bf16.h>
#include <cstdint>

// ---------------- Problem constants ----------------
#define N_NODES 210
#define N_EDGES 4200
#define BATCH   32

// ---------------- Static device scratch ----------------
__device__ float    g_bufA[32ll * 56 * 210 * 64];   // 24.08M floats
__device__ float    g_bufB[32ll * 56 * 210 * 64];
__device__ float    g_bufC[32ll * 48 * 210 * 128];  // 41.29M floats
__device__ int      g_rowptr[N_NODES + 1];
__device__ int      g_cols[N_EDGES];
__device__ float    g_norm[N_EDGES];
__device__ uint32_t g_wt[387072];                   // tf32 tconv weights
__device__ float    g_m1[N_NODES * N_NODES];        // dense Lhat
__device__ float    g_mc_hi[448 * 216];             // [M1 ; 2M1^2 - I] tf32-hi
__device__ float    g_mc_lo[448 * 216];             // residual tf32-lo
__device__ uint32_t g_bp[2 * 13824];                // cheb W images (192x72) x2

// region offsets in g_wt
#define WOFF1 0        // b1_t1 padded (3,9,16,64)   = 27648
#define WOFF2 27648    // b1_t2        (3,9,64,128)  = 221184
#define WOFF3 248832   // b2_t1        (3,5,128,64)  = 122880
#define WOFF4 371712   // b2_t2        (3,5,64,16)   = 15360

// ---------------- helpers ----------------
__device__ __forceinline__ uint32_t f2tf32v(float x) {
    uint32_t r; asm("cvt.rna.tf32.f32 %0, %1;" : "=r"(r) : "f"(x)); return r;
}
__device__ __forceinline__ float roundtf(float x) {
    return __uint_as_float(f2tf32v(x));
}
__device__ __forceinline__ void mma_tf32(float c[4], const uint32_t a[4], const uint32_t b[2]) {
    asm volatile("mma.sync.aligned.m16n8k8.row.col.f32.tf32.tf32.f32 "
        "{%0,%1,%2,%3}, {%4,%5,%6,%7}, {%8,%9}, {%0,%1,%2,%3};"
        : "+f"(c[0]), "+f"(c[1]), "+f"(c[2]), "+f"(c[3])
        : "r"(a[0]), "r"(a[1]), "r"(a[2]), "r"(a[3]), "r"(b[0]), "r"(b[1]));
}
__device__ __forceinline__ uint32_t sptr(const void* p) {
    return (uint32_t)__cvta_generic_to_shared(p);
}
__device__ __forceinline__ void cpa16(uint32_t dst, const void* src, int sz) {
    asm volatile("cp.async.cg.shared.global [%0], [%1], 16, %2;"
                 :: "r"(dst), "l"(src), "r"(sz));
}
__device__ __forceinline__ void cpa_commit() { asm volatile("cp.async.commit_group;"); }
__device__ __forceinline__ void cpa_waitall() { asm volatile("cp.async.wait_group 0;"); }

// ---------------- Weight prepass: fp32 -> tf32 (padded for b1_t1) ----------------
__global__ void wconv_kernel(const float* __restrict__ w1, const float* __restrict__ w2,
                             const float* __restrict__ w3, const float* __restrict__ w4,
                             uint32_t* __restrict__ out)
{
    int i = blockIdx.x * blockDim.x + threadIdx.x;
    if (i < 27648) {  // b1_t1 padded: (g,k,ci<16,co<64); src (3,1,9,14,64)
        int co = i & 63; int r = i >> 6;
        int ci = r % 16; r /= 16;
        int k = r % 9;  int g = r / 9;
        float v = (ci < 14) ? w1[((g * 9 + k) * 14 + ci) * 64 + co] : 0.f;
        out[i] = f2tf32v(v);
        return;
    }
    int j = i - WOFF2;
    if (j >= 0 && j < 221184) { out[i] = f2tf32v(w2[j]); return; }
    j = i - WOFF3;
    if (j >= 0 && j < 122880) { out[i] = f2tf32v(w3[j]); return; }
    j = i - WOFF4;
    if (j >= 0 && j < 15360)  { out[i] = f2tf32v(w4[j]); return; }
}

// ---------------- CSR build (deterministic, 1 block) ----------------
__global__ void build_csr_kernel(const int* __restrict__ edge_index,
                                 const float* __restrict__ eattr,
                                 int* __restrict__ rowptr,
                                 int* __restrict__ cols,
                                 float* __restrict__ norms)
{
    __shared__ int   row_s[N_EDGES];
    __shared__ short col_s[N_EDGES];
    __shared__ float attr_s[N_EDGES];
    __shared__ int   cnt_s[N_NODES + 1];
    __shared__ float dis_s[N_NODES];

    const int tid = threadIdx.x;  // 256
    for (int i = tid; i < N_EDGES; i += 256) {
        row_s[i]  = edge_index[i];
        col_s[i]  = (short)edge_index[N_EDGES + i];
        attr_s[i] = eattr[i];
    }
    __syncthreads();

    if (tid < N_NODES) {
        float deg = 0.f; int cnt = 0;
        for (int e = 0; e < N_EDGES; e++) {
            if (row_s[e] == tid) { deg += attr_s[e]; cnt++; }
        }
        cnt_s[tid] = cnt;
        dis_s[tid] = (deg > 0.f) ? rsqrtf(deg) : 0.f;
    }
    __syncthreads();
    if (tid == 0) {
        int acc = 0;
        for (int n = 0; n < N_NODES; n++) { int c = cnt_s[n]; cnt_s[n] = acc; acc += c; }
        cnt_s[N_NODES] = acc;
    }
    __syncthreads();
    if (tid <= N_NODES) rowptr[tid] = cnt_s[tid];
    if (tid < N_NODES) {
        int wpos = cnt_s[tid];
        const float disr = dis_s[tid];
        for (int e = 0; e < N_EDGES; e++) {
            if (row_s[e] == tid) {
                int c = col_s[e];
                cols[wpos]  = c;
                norms[wpos] = -disr * attr_s[e] * dis_s[c];
                wpos++;
            }
        }
    }
}

// ---------------- Dense M1 from CSR (1 block) ----------------
__global__ void m1_build_kernel(const int* __restrict__ rowptr, const int* __restrict__ cols,
                                const float* __restrict__ norms)
{
    const int tid = threadIdx.x;  // 1024
    for (int i = tid; i < N_NODES * N_NODES; i += 1024) g_m1[i] = 0.f;
    __syncthreads();
    if (tid < N_NODES) {
        int s = rowptr[tid], e = rowptr[tid + 1];
        for (int i = s; i < e; i++)
            g_m1[tid * N_NODES + cols[i]] += norms[i];
    }
}

// ---------------- Mc = [[M1];[2*M1^2 - I]] as tf32 hi/lo (grid 448) ----------------
__global__ void mc_build_kernel()
{
    const int m = blockIdx.x;       // 0..447
    const int k = threadIdx.x;      // 256
    if (k >= 216) return;
    float v = 0.f;
    if (m < 224) {
        if (m < N_NODES && k < N_NODES) v = g_m1[m * N_NODES + k];
    } else {
        int r = m - 224;
        if (r < N_NODES && k < N_NODES) {
            float s = 0.f;
            for (int j = 0; j < N_NODES; j++)
                s = fmaf(g_m1[r * N_NODES + j], g_m1[j * N_NODES + k], s);
            v = 2.f * s - (k == r ? 1.f : 0.f);
        }
    }
    uint32_t hi = f2tf32v(v);
    g_mc_hi[m * 216 + k] = __uint_as_float(hi);
    g_mc_lo[m * 216 + k] = __uint_as_float(f2tf32v(v - __uint_as_float(hi)));
}

// ---------------- Cheb W images: plain tf32 [W0;W1;W2] at stride 72 ----------------
__global__ void bp_build_kernel(const float* __restrict__ W1, const float* __restrict__ W2)
{
    int i = blockIdx.x * blockDim.x + threadIdx.x;
    if (i >= 2 * 13824) return;
    int which = i / 13824, r = i % 13824;
    int row = r / 72, g = r % 72;
    const float* W = which ? W2 : W1;
    float v = (g < 64) ? W[row * 64 + g] : 0.f;
    g_bp[i] = f2tf32v(v);
}

// ---------------- Gated temporal conv via tf32 mma.sync ----------------
// 2 m-tiles per warp: B fragments reused across both -> smem bytes/mma halved.
template<int Cin, int CINP, int Cout, int Kt, int Tin, int Tout, int TP, int NG,
         int KSUB, int CO, bool ACP, int MINB>
__global__ void __launch_bounds__((NG * (TP / 16) / 2) * 32, MINB)
tconv_mma(const float* __restrict__ x, const uint32_t* __restrict__ wt,
          const float* __restrict__ bias, float* __restrict__ out)
{
    constexpr int MTN   = TP / 16;         // m-tiles per node
    constexpr int TILES = NG * MTN;
    constexpr int NW    = TILES / 2;       // warps (2 tiles per warp)
    constexpr int THREADS = NW * 32;
    constexpr int XS    = TP + Kt - 1;
    constexpr int SA    = CINP + 4;
    constexpr int COLS  = 3 * CO;
    constexpr int SB    = COLS + 8;
    constexpr int NT    = COLS / 8;
    constexpr int COCH  = Cout / CO;
    constexpr int NKS   = CINP / KSUB;
    constexpr int KPI   = Kt * NKS;
    constexpr int ITERS = COCH * KPI;
    constexpr int BUFSZ = KSUB * SB;
    constexpr int CO4   = CO / 4;
    static_assert(TILES % 2 == 0, "even tiles");

    extern __shared__ uint32_t sh[];
    uint32_t* As = sh;                  // NG*XS*SA
    uint32_t* Bs = sh + NG * XS * SA;   // 2*BUFSZ

    const int n0  = blockIdx.x * NG;
    const int b   = blockIdx.y;
    const int tid = threadIdx.x;
    const int wid = tid >> 5, lane = tid & 31;
    const int gid = lane >> 2, tig = lane & 3;

    const int tile0 = 2 * wid, tile1 = 2 * wid + 1;
    const int nl[2]  = { tile0 / MTN, tile1 / MTN };
    const int t0s[2] = { (tile0 % MTN) * 16, (tile1 % MTN) * 16 };

    // ---- stage A slab ----
    if (ACP) {
        constexpr int C4 = CINP / 4;
        for (int i = tid; i < NG * XS * C4; i += THREADS) {
            int nlx = i / (XS * C4);
            int r   = i % (XS * C4);
            int tp = r / C4, c4 = r % C4;
            int nn = n0 + nlx;
            bool ok = (nn < N_NODES) && (tp < Tin);
            const float* src = x + ((size_t)(b * Tin + (ok ? tp : 0)) * N_NODES
                                    + (nn < N_NODES ? nn : 0)) * Cin + c4 * 4;
            cpa16(sptr(As + nlx * XS * SA + tp * SA + c4 * 4), src, ok ? 16 : 0);
        }
    } else {
        for (int i = tid; i < NG * XS * CINP; i += THREADS) {
            int nlx = i / (XS * CINP);
            int r   = i % (XS * CINP);
            int tp = r / CINP, ci = r % CINP;
            int nn = n0 + nlx;
            float v = 0.f;
            if (nn < N_NODES && tp < Tin && ci < Cin)
                v = x[((size_t)(b * Tin + tp) * N_NODES + nn) * Cin + ci];
            As[nlx * XS * SA + tp * SA + ci] = f2tf32v(v);
        }
    }

    // ---- B stage (cp.async) ----
    auto stageB = [&](int it) {
        int cc = it / KPI, r = it % KPI, k = r / NKS, ks = r % NKS;
        uint32_t* Bb = Bs + (it & 1) * BUFSZ;
        for (int i = tid; i < KSUB * 3 * CO4; i += THREADS) {
            int cil = i / (3 * CO4);
            int rr  = i % (3 * CO4);
            int g   = rr / CO4, c4 = rr % CO4;
            const uint32_t* src = wt + ((size_t)(g * Kt + k) * CINP + ks * KSUB + cil) * Cout
                                     + cc * CO + c4 * 4;
            cpa16(sptr(Bb + cil * SB + g * CO + c4 * 4), src, 16);
        }
    };

    stageB(0);
    cpa_commit();

    const uint32_t* A0 = As + nl[0] * XS * SA;
    const uint32_t* A1 = As + nl[1] * XS * SA;

    float acc[2][NT][4];
    #pragma unroll
    for (int m = 0; m < 2; m++)
        #pragma unroll
        for (int i = 0; i < NT; i++) { acc[m][i][0] = acc[m][i][1] = acc[m][i][2] = acc[m][i][3] = 0.f; }

    #pragma unroll 1
    for (int it = 0; it < ITERS; ++it) {
        cpa_waitall();
        __syncthreads();
        if (it + 1 < ITERS) { stageB(it + 1); cpa_commit(); }

        const int r = it % KPI, k = r / NKS, ks = r % NKS;
        const uint32_t* Bb = Bs + (it & 1) * BUFSZ;
        #pragma unroll
        for (int kk = 0; kk < KSUB / 8; kk++) {
            uint32_t a0[4], a1[4];
            {
                const uint32_t* ap = A0 + (t0s[0] + gid + k) * SA + ks * KSUB + kk * 8 + tig;
                a0[0] = ap[0]; a0[1] = ap[8 * SA]; a0[2] = ap[4]; a0[3] = ap[8 * SA + 4];
            }
            {
                const uint32_t* ap = A1 + (t0s[1] + gid + k) * SA + ks * KSUB + kk * 8 + tig;
                a1[0] = ap[0]; a1[1] = ap[8 * SA]; a1[2] = ap[4]; a1[3] = ap[8 * SA + 4];
            }
            #pragma unroll
            for (int nt = 0; nt < NT; nt++) {
                const uint32_t* bp = Bb + (kk * 8 + tig) * SB + nt * 8 + gid;
                uint32_t bf[2] = { bp[0], bp[4 * SB] };
                mma_tf32(acc[0][nt], a0, bf);
                mma_tf32(acc[1][nt], a1, bf);
            }
        }

        if ((it + 1) % KPI == 0) {
            const int cc = it / KPI;
            #pragma unroll
            for (int m = 0; m < 2; m++) {
                const int n = n0 + nl[m];
                if (n < N_NODES) {
                    #pragma unroll
                    for (int nt3 = 0; nt3 < NT / 3; nt3++) {
                        int co = cc * CO + nt3 * 8 + tig * 2;
                        float bP0 = bias[co],            bP1 = bias[co + 1];
                        float bQ0 = bias[Cout + co],     bQ1 = bias[Cout + co + 1];
                        float bR0 = bias[2 * Cout + co], bR1 = bias[2 * Cout + co + 1];
                        #pragma unroll
                        for (int half = 0; half < 2; half++) {
                            int t = t0s[m] + gid + half * 8;
                            if (t < Tout) {
                                int i0 = half * 2;
                                float P0 = acc[m][nt3][i0] + bP0;
                                float P1 = acc[m][nt3][i0 + 1] + bP1;
                                float Q0 = acc[m][nt3 + NT / 3][i0] + bQ0;
                                float Q1 = acc[m][nt3 + NT / 3][i0 + 1] + bQ1;
                                float R0 = acc[m][nt3 + 2 * NT / 3][i0] + bR0;
                                float R1 = acc[m][nt3 + 2 * NT / 3][i0 + 1] + bR1;
                                float v0 = fmaxf(fmaf(P0, 1.f / (1.f + __expf(-Q0)), R0), 0.f);
                                float v1 = fmaxf(fmaf(P1, 1.f / (1.f + __expf(-Q1)), R1), 0.f);
                                *(float2*)&out[((size_t)(b * Tout + t) * N_NODES + n) * Cout + co] =
                                    make_float2(v0, v1);
                            }
                        }
                    }
                }
            }
            #pragma unroll
            for (int m = 0; m < 2; m++)
                #pragma unroll
                for (int i = 0; i < NT; i++) { acc[m][i][0] = acc[m][i][1] = acc[m][i][2] = acc[m][i][3] = 0.f; }
        }
    }
}

// ---------------- Chebyshev: two fused tensor GEMMs, zero scalar gather ----------------
// Phase 1: [t1;t2](448x64) = Mc(448x216, hi+lo streamed from L2) @ z(216x64 smem)
// Phase 2: out = relu([t0|t1|t2](210x192) @ [W0;W1;W2](192x64) + bias)
__global__ void __launch_bounds__(896, 1)
cheb_mma2_kernel(const float* __restrict__ zin, const float* __restrict__ mch,
                 const float* __restrict__ mcl, const uint32_t* __restrict__ bpimg,
                 const float* __restrict__ bias, float* __restrict__ out)
{
    extern __shared__ float fs[];
    float* A_all = fs;                              // 224 x 196
    uint32_t* SB = (uint32_t*)(fs + 224 * 196);     // union: 2x(448x12) stream bufs / 192x72 W image

    const int bt  = blockIdx.x;
    const int tid = threadIdx.x;
    const int wid = tid >> 5, lane = tid & 31;
    const int gid = lane >> 2, tig = lane & 3;
    const size_t base = (size_t)bt * N_NODES * 64;

    // stage z into cols [0,64); zero rows 210..223 across full width
    {
        const float4* zin4 = (const float4*)(zin + base);
        for (int i = tid; i < N_NODES * 16; i += 896) {
            int n = i >> 4, c4 = i & 15;
            *(float4*)&A_all[n * 196 + c4 * 4] = zin4[i];
        }
        for (int i = tid; i < 14 * 196; i += 896)
            A_all[(210 + i / 196) * 196 + (i % 196)] = 0.f;
    }

    // Mc chunk staging: it = 2*c + plane; chunk = 448 rows x 8 k-cols, smem stride 12
    auto stageMc = [&](int it) {
        int plane = it & 1, c = it >> 1;
        const float* src = (plane ? mcl : mch) + c * 8;
        uint32_t* Bb = SB + (it & 1) * 5376;
        int m = tid >> 1, half = tid & 1;   // 896 threads = 448*2 exactly
        cpa16(sptr(Bb + m * 12 + half * 4), src + (size_t)m * 216 + half * 4, 16);
    };
    stageMc(0); cpa_commit();
    __syncthreads();   // z + pads visible

    // ---- Phase 1 GEMM: 28 warps x 1 m-tile, N=64, K=216 (27 k8-chunks x hi/lo) ----
    const int m0 = wid * 16;
    float accg[8][4];
    #pragma unroll
    for (int i = 0; i < 8; i++) { accg[i][0] = accg[i][1] = accg[i][2] = accg[i][3] = 0.f; }

    #pragma unroll 1
    for (int c = 0; c < 27; c++) {
        // B fragments from z (shared across hi and lo planes)
        uint32_t bfr[8][2];
        #pragma unroll
        for (int nt = 0; nt < 8; nt++) {
            const uint32_t* bp = (const uint32_t*)A_all + (c * 8 + tig) * 196 + nt * 8 + gid;
            bfr[nt][0] = bp[0]; bfr[nt][1] = bp[4 * 196];
        }
        #pragma unroll
        for (int p = 0; p < 2; p++) {
            int it = 2 * c + p;
            cpa_waitall();
            __syncthreads();
            if (it + 1 < 54) { stageMc(it + 1); cpa_commit(); }
            const uint32_t* Ac = SB + (it & 1) * 5376;
            uint32_t a[4];
            a[0] = Ac[(m0 + gid) * 12 + tig];
            a[1] = Ac[(m0 + gid + 8) * 12 + tig];
            a[2] = Ac[(m0 + gid) * 12 + 4 + tig];
            a[3] = Ac[(m0 + gid + 8) * 12 + 4 + tig];
            #pragma unroll
            for (int nt = 0; nt < 8; nt++) mma_tf32(accg[nt], a, bfr[nt]);
        }
    }

    // epilogue: write t1 (warps 0-13 -> cols 64..127), t2 (warps 14-27 -> cols 128..191)
    {
        const int colb = (wid < 14) ? 64 : 128;
        const int rowb = (wid < 14) ? wid * 16 : (wid - 14) * 16;
        #pragma unroll
        for (int nt = 0; nt < 8; nt++) {
            *(float2*)&A_all[(rowb + gid) * 196 + colb + nt * 8 + tig * 2] =
                make_float2(accg[nt][0], accg[nt][1]);
            *(float2*)&A_all[(rowb + gid + 8) * 196 + colb + nt * 8 + tig * 2] =
                make_float2(accg[nt][2], accg[nt][3]);
        }
    }
    __syncthreads();

    // stage W image over the stream-buffer region
    for (int i = tid; i < 3456; i += 896)
        cpa16(sptr(SB + i * 4), bpimg + i * 4, 16);
    cpa_commit(); cpa_waitall();
    __syncthreads();

    // ---- Phase 2 combine: 28 warps = 14 m-tiles x 2 n-halves, K=192 ----
    {
        const int mt = wid >> 1, nh = wid & 1;
        const int cm0 = mt * 16;
        float acc[4][4];
        #pragma unroll
        for (int i = 0; i < 4; i++) { acc[i][0] = acc[i][1] = acc[i][2] = acc[i][3] = 0.f; }

        #pragma unroll 4
        for (int kk = 0; kk < 24; kk++) {
            const float* ap = A_all + (cm0 + gid) * 196 + kk * 8 + tig;
            float af[4] = { ap[0], ap[8 * 196], ap[4], ap[8 * 196 + 4] };
            uint32_t hi[4], lo[4];
            #pragma unroll
            for (int e = 0; e < 4; e++) {
                hi[e] = f2tf32v(af[e]);
                lo[e] = f2tf32v(af[e] - __uint_as_float(hi[e]));
            }
            #pragma unroll
            for (int j = 0; j < 4; j++) {
                int nt = nh * 4 + j;
                const uint32_t* bp = SB + (kk * 8 + tig) * 72 + nt * 8 + gid;
                uint32_t bf[2] = { bp[0], bp[4 * 72] };
                mma_tf32(acc[j], hi, bf);
                if (kk >= 8) mma_tf32(acc[j], lo, bf);   // z cols are tf32-exact
            }
        }

        #pragma unroll
        for (int j = 0; j < 4; j++) {
            int g = (nh * 4 + j) * 8 + tig * 2;
            float b0 = bias[g], b1 = bias[g + 1];
            int n_lo = cm0 + gid, n_hi2 = cm0 + gid + 8;
            if (n_lo < N_NODES) {
                float v0 = roundtf(fmaxf(acc[j][0] + b0, 0.f));
                float v1 = roundtf(fmaxf(acc[j][1] + b1, 0.f));
                *(float2*)&out[base + (size_t)n_lo * 64 + g] = make_float2(v0, v1);
            }
            if (n_hi2 < N_NODES) {
                float v0 = roundtf(fmaxf(acc[j][2] + b0, 0.f));
                float v1 = roundtf(fmaxf(acc[j][3] + b1, 0.f));
                *(float2*)&out[base + (size_t)n_hi2 * 64 + g] = make_float2(v0, v1);
            }
        }
    }
}

// ---------------- BatchNorm over node channel (in-place, float4) ----------------
template<int C, bool RND>
__global__ void bn_kernel(float* __restrict__ x, const float* __restrict__ gamma,
                          const float* __restrict__ beta, int BT, int N)
{
    constexpr int C4 = C / 4;
    const int n   = blockIdx.x;
    const int tid = threadIdx.x;  // 256
    const int M4  = BT * C4;
    float4* x4 = (float4*)x;
    float s = 0.f, s2 = 0.f;
    for (int i = tid; i < M4; i += 256) {
        int bt = i / C4, c4 = i % C4;
        float4 v = x4[((size_t)bt * N + n) * C4 + c4];
        s  += v.x + v.y + v.z + v.w;
        s2 += v.x * v.x + v.y * v.y + v.z * v.z + v.w * v.w;
    }
    __shared__ float rs[256], rs2[256];
    __shared__ float mean_s, istd_s;
    rs[tid] = s; rs2[tid] = s2;
    __syncthreads();
    for (int o = 128; o > 0; o >>= 1) {
        if (tid < o) { rs[tid] += rs[tid + o]; rs2[tid] += rs2[tid + o]; }
        __syncthreads();
    }
    if (tid == 0) {
        float inv = 1.f / (float)(BT * C);
        float mean = rs[0] * inv;
        float var  = rs2[0] * inv - mean * mean;
        mean_s = mean;
        istd_s = rsqrtf(var + 1e-5f);
    }
    __syncthreads();
    const float gm = gamma[n], bt_ = beta[n];
    const float mean = mean_s, istd = istd_s;
    for (int i = tid; i < M4; i += 256) {
        int bt = i / C4, c4 = i % C4;
        size_t a = ((size_t)bt * N + n) * C4 + c4;
        float4 v = x4[a];
        v.x = (v.x - mean) * istd * gm + bt_;
        v.y = (v.y - mean) * istd * gm + bt_;
        v.z = (v.z - mean) * istd * gm + bt_;
        v.w = (v.w - mean) * istd * gm + bt_;
        if (RND) { v.x = roundtf(v.x); v.y = roundtf(v.y); v.z = roundtf(v.z); v.w = roundtf(v.w); }
        x4[a] = v;
    }
}

// ---------------- Final FC: (R,16) @ (16,3) + b ----------------
__global__ void fc_kernel(const float* __restrict__ h, const float* __restrict__ w,
                          const float* __restrict__ b, float* __restrict__ out, int R)
{
    int r = blockIdx.x * blockDim.x + threadIdx.x;
    if (r >= R) return;
    const float4* hr = (const float4*)(h + (size_t)r * 16);
    float o0 = b[0], o1 = b[1], o2 = b[2];
    #pragma unroll
    for (int c4 = 0; c4 < 4; c4++) {
        float4 v = hr[c4];
        o0 = fmaf(v.x, w[(c4 * 4 + 0) * 3 + 0], o0); o1 = fmaf(v.x, w[(c4 * 4 + 0) * 3 + 1], o1); o2 = fmaf(v.x, w[(c4 * 4 + 0) * 3 + 2], o2);
        o0 = fmaf(v.y, w[(c4 * 4 + 1) * 3 + 0], o0); o1 = fmaf(v.y, w[(c4 * 4 + 1) * 3 + 1], o1); o2 = fmaf(v.y, w[(c4 * 4 + 1) * 3 + 2], o2);
        o0 = fmaf(v.z, w[(c4 * 4 + 2) * 3 + 0], o0); o1 = fmaf(v.z, w[(c4 * 4 + 2) * 3 + 1], o1); o2 = fmaf(v.z, w[(c4 * 4 + 2) * 3 + 2], o2);
        o0 = fmaf(v.w, w[(c4 * 4 + 3) * 3 + 0], o0); o1 = fmaf(v.w, w[(c4 * 4 + 3) * 3 + 1], o1); o2 = fmaf(v.w, w[(c4 * 4 + 3) * 3 + 2], o2);
    }
    out[(size_t)r * 3 + 0] = o0;
    out[(size_t)r * 3 + 1] = o1;
    out[(size_t)r * 3 + 2] = o2;
}

// ---------------- Launch ----------------
extern "C" void kernel_launch(void* const* d_in, const int* in_sizes, int n_in,
                              void* d_out, int out_size)
{
    const float* x        = (const float*)d_in[0];
    const int*   eidx     = (const int*)d_in[1];
    const float* eattr    = (const float*)d_in[2];
    const float* b1_t1_w  = (const float*)d_in[3];
    const float* b1_t1_b  = (const float*)d_in[4];
    const float* b1_ch_w  = (const float*)d_in[5];
    const float* b1_ch_b  = (const float*)d_in[6];
    const float* b1_t2_w  = (const float*)d_in[7];
    const float* b1_t2_b  = (const float*)d_in[8];
    const float* b1_bn_g  = (const float*)d_in[9];
    const float* b1_bn_b  = (const float*)d_in[10];
    const float* b2_t1_w  = (const float*)d_in[11];
    const float* b2_t1_b  = (const float*)d_in[12];
    const float* b2_ch_w  = (const float*)d_in[13];
    const float* b2_ch_b  = (const float*)d_in[14];
    const float* b2_t2_w  = (const float*)d_in[15];
    const float* b2_t2_b  = (const float*)d_in[16];
    const float* b2_bn_g  = (const float*)d_in[17];
    const float* b2_bn_b  = (const float*)d_in[18];
    const float* fc_w     = (const float*)d_in[19];
    const float* fc_b     = (const float*)d_in[20];

    float *bufA, *bufB, *bufC, *nrm, *mch, *mcl;
    int *rowptr, *cols; uint32_t *wt, *bp;
    cudaGetSymbolAddress((void**)&bufA,  g_bufA);
    cudaGetSymbolAddress((void**)&bufB,  g_bufB);
    cudaGetSymbolAddress((void**)&bufC,  g_bufC);
    cudaGetSymbolAddress((void**)&rowptr, g_rowptr);
    cudaGetSymbolAddress((void**)&cols,  g_cols);
    cudaGetSymbolAddress((void**)&nrm,   g_norm);
    cudaGetSymbolAddress((void**)&wt,    g_wt);
    cudaGetSymbolAddress((void**)&mch,   g_mc_hi);
    cudaGetSymbolAddress((void**)&mcl,   g_mc_lo);
    cudaGetSymbolAddress((void**)&bp,    g_bp);

    const int N = N_NODES;

    // instantiations:           Cin CINP Cout Kt Tin Tout TP NG KSUB CO  ACP  MINB
    auto k_b1t1 = tconv_mma<14, 16, 64, 9, 64, 56, 64, 4, 16, 32, false, 2>;  // 8 warps, 2 blk/SM
    auto k_b1t2 = tconv_mma<64, 64, 128, 9, 56, 48, 48, 4, 64, 32, true, 2>;  // 6 warps, 2 blk/SM
    auto k_b2t1 = tconv_mma<128, 128, 64, 5, 48, 44, 48, 6, 64, 32, true, 1>; // 9 warps, 1 blk/SM
    auto k_b2t2 = tconv_mma<64, 64, 16, 5, 44, 40, 48, 4, 64, 16, true, 2>;   // 6 warps, 2 blk/SM

    // smem bytes: (NG*XS*SA + 2*KSUB*SB) * 4
    const int sm_b1t1 = (4 * 72 * 20 + 2 * 16 * 104) * 4;    // 36,352
    const int sm_b1t2 = (4 * 56 * 68 + 2 * 64 * 104) * 4;    // 114,176
    const int sm_b2t1 = (6 * 52 * 132 + 2 * 64 * 104) * 4;   // 217,984
    const int sm_b2t2 = (4 * 52 * 68 + 2 * 64 * 56) * 4;     // 85,248
    const int sm_cheb = (224 * 196 + 13824) * 4;             // 230,912

    cudaFuncSetAttribute(k_b1t1, cudaFuncAttributeMaxDynamicSharedMemorySize, sm_b1t1);
    cudaFuncSetAttribute(k_b1t2, cudaFuncAttributeMaxDynamicSharedMemorySize, sm_b1t2);
    cudaFuncSetAttribute(k_b2t1, cudaFuncAttributeMaxDynamicSharedMemorySize, sm_b2t1);
    cudaFuncSetAttribute(k_b2t2, cudaFuncAttributeMaxDynamicSharedMemorySize, sm_b2t2);
    cudaFuncSetAttribute(cheb_mma2_kernel, cudaFuncAttributeMaxDynamicSharedMemorySize, sm_cheb);

    // ---- prep ----
    build_csr_kernel<<<1, 256>>>(eidx, eattr, rowptr, cols, nrm);
    wconv_kernel<<<(387072 + 255) / 256, 256>>>(b1_t1_w, b1_t2_w, b2_t1_w, b2_t2_w, wt);
    m1_build_kernel<<<1, 1024>>>(rowptr, cols, nrm);
    mc_build_kernel<<<448, 256>>>();
    bp_build_kernel<<<(2 * 13824 + 255) / 256, 256>>>(b1_ch_w, b2_ch_w);

    // ======== Block 1 ========
    k_b1t1<<<dim3(53, BATCH), 256, sm_b1t1>>>(x, wt + WOFF1, b1_t1_b, bufA);
    cheb_mma2_kernel<<<32 * 56, 896, sm_cheb>>>(bufA, mch, mcl, bp, b1_ch_b, bufB);
    k_b1t2<<<dim3(53, BATCH), 192, sm_b1t2>>>(bufB, wt + WOFF2, b1_t2_b, bufC);
    bn_kernel<128, true><<<N, 256>>>(bufC, b1_bn_g, b1_bn_b, 32 * 48, N);

    // ======== Block 2 ========
    k_b2t1<<<dim3(35, BATCH), 288, sm_b2t1>>>(bufC, wt + WOFF3, b2_t1_b, bufA);
    cheb_mma2_kernel<<<32 * 44, 896, sm_cheb>>>(bufA, mch, mcl, bp + 13824, b2_ch_b, bufB);
    k_b2t2<<<dim3(53, BATCH), 192, sm_b2t2>>>(bufB, wt + WOFF4, b2_t2_b, bufC);
    bn_kernel<16, false><<<N, 256>>>(bufC, b2_bn_g, b2_bn_b, 32 * 40, N);

    // ---- FC ----
    {
        int R = 32 * 40 * N;  // 268800
        fc_kernel<<<(R + 255) / 256, 256>>>(bufC, fc_w, fc_b, (float*)d_out, R);
    }
    (void)in_sizes; (void)n_in; (void)out_size;
}